// round 13
// baseline (speedup 1.0000x reference)
#include <cuda_runtime.h>
#include <cuda_bf16.h>
#include <cstdint>

#define B_DIM 2048
#define NLEAF 1024

// ---------------- device scratch (no allocations allowed) ----------------
__device__ __align__(256) float g_bufA[(size_t)B_DIM * NLEAF * 32];        // 256 MB
__device__ __align__(256) float g_bufB[(size_t)B_DIM * (NLEAF / 2) * 32];  // 128 MB
// per-MLP weight stage: W1t hi/lo [128][104], W2t hi/lo [128][136], W3t hi/lo [32][136]
#define W1_ELEMS 13312  // 128*104
#define W2_ELEMS 17408  // 128*136
#define W3_ELEMS 4352   // 32*136
#define STAGE_BYTES 140288
__device__ __align__(256) unsigned char g_wstage[2 * STAGE_BYTES];

// ---------------- smem layout (bytes) ----------------
#define OFF_W1H 0
#define OFF_W1L 26624
#define OFF_W2H 53248
#define OFF_W2L 88064
#define OFF_W3H 122880
#define OFF_W3L 131584
#define OFF_BIAS 140288  // b1(128f) b2(128f) b3(32f) = 1152B
#define OFF_A 141440     // 2 groups x (64x136 bf16 hi + lo) = 2 x 34816
#define GRP_A_BYTES 34816
#define GRP_A_LO 17408
#define SM_BYTES 211072

#define A_STRIDE 272  // bytes per A row (136 bf16); 272 % 128 = 16 -> conflict-free LDSM
#define W1_KP 104     // 208B stride; 208 % 128 = 80 -> conflict-free
#define W23_KP 136

// ---------------- PTX helpers (base-arch only: ldmatrix + mma.sync) ----------------
__device__ __forceinline__ uint32_t smem_u32(const void* p) {
    uint32_t a;
    asm("{ .reg .u64 t; cvta.to.shared.u64 t, %1; cvt.u32.u64 %0, t; }" : "=r"(a) : "l"(p));
    return a;
}
__device__ __forceinline__ void bar_grp(int g) {
    asm volatile("bar.sync %0, 128;" ::"r"(g + 1) : "memory");
}
__device__ __forceinline__ uint4 ldsm4(uint32_t a) {
    uint4 r;
    asm volatile("ldmatrix.sync.aligned.m8n8.x4.shared.b16 {%0,%1,%2,%3}, [%4];"
                 : "=r"(r.x), "=r"(r.y), "=r"(r.z), "=r"(r.w)
                 : "r"(a));
    return r;
}
__device__ __forceinline__ void mma_bf16(float* c, const uint4& a, uint32_t b0, uint32_t b1) {
    asm volatile(
        "mma.sync.aligned.m16n8k16.row.col.f32.bf16.bf16.f32 "
        "{%0,%1,%2,%3}, {%4,%5,%6,%7}, {%8,%9}, {%0,%1,%2,%3};"
        : "+f"(c[0]), "+f"(c[1]), "+f"(c[2]), "+f"(c[3])
        : "r"(a.x), "r"(a.y), "r"(a.z), "r"(a.w), "r"(b0), "r"(b1));
}

// ---------------- bf16 hi/lo split ----------------
__device__ __forceinline__ void split2(float x, float y, uint32_t& h, uint32_t& l) {
    __nv_bfloat16 hx = __float2bfloat16(x), hy = __float2bfloat16(y);
    float rx = x - __bfloat162float(hx), ry = y - __bfloat162float(hy);
    __nv_bfloat16 lx = __float2bfloat16(rx), ly = __float2bfloat16(ry);
    h = (uint32_t)__bfloat16_as_ushort(hx) | ((uint32_t)__bfloat16_as_ushort(hy) << 16);
    l = (uint32_t)__bfloat16_as_ushort(lx) | ((uint32_t)__bfloat16_as_ushort(ly) << 16);
}
// store 4 consecutive k of row into A_hi/A_lo (row-major, stride 136 bf16)
__device__ __forceinline__ void store4A(char* aHi, char* aLo, int row, int k, float4 v) {
    uint32_t h0, l0, h1, l1;
    split2(v.x, v.y, h0, l0);
    split2(v.z, v.w, h1, l1);
    uint32_t off = (uint32_t)row * A_STRIDE + (uint32_t)k * 2;
    *(uint2*)(aHi + off) = make_uint2(h0, h1);
    *(uint2*)(aLo + off) = make_uint2(l0, l1);
}

__device__ __forceinline__ void copy4(float* dst, const float* __restrict__ src, int nfloats) {
    const float4* s = (const float4*)src;
    float4* d = (float4*)dst;
    int n4 = nfloats >> 2;
    for (int i = threadIdx.x; i < n4; i += blockDim.x) d[i] = s[i];
}

// ---------------- one layer: per-warp C[32 x (NTILES*8)], 3-term split ----------------
// ks loop fully unrolled (ptxas pipelines LDSM across MMA groups).
// B fragments via ldsm4: lanes 0-15 -> rows n..n+7 x two k-halves (nt even),
// lanes 16-31 -> rows n+8..n+15 (nt odd). r.xy / r.zw = the two nt fragments.
template <int NK, int NTILES, int WKP>
__device__ __forceinline__ void layer_mma(uint32_t aHiB, uint32_t aLoB, uint32_t wHiB,
                                          uint32_t wLoB, float c[2][NTILES][4], int m0, int n0) {
    const int lane = threadIdx.x & 31;
#pragma unroll
    for (int mt = 0; mt < 2; mt++)
#pragma unroll
        for (int nt = 0; nt < NTILES; nt++)
#pragma unroll
            for (int j = 0; j < 4; j++) c[mt][nt][j] = 0.f;

    uint32_t aOff = (uint32_t)(m0 + (lane & 15)) * A_STRIDE + (uint32_t)((lane >> 4) << 4);
    uint32_t aH = aHiB + aOff, aL = aLoB + aOff;
    uint32_t wOff = (uint32_t)(n0 + (lane & 7) + ((lane >> 4) << 3)) * (WKP * 2) +
                    (uint32_t)(((lane >> 3) & 1) << 4);
    uint32_t wH = wHiB + wOff, wL = wLoB + wOff;

#pragma unroll
    for (int ks = 0; ks < NK; ks++) {
        uint32_t ka = (uint32_t)ks * 32;
        uint4 ah0 = ldsm4(aH + ka);
        uint4 ah1 = ldsm4(aH + 16 * A_STRIDE + ka);
        uint4 al0 = ldsm4(aL + ka);
        uint4 al1 = ldsm4(aL + 16 * A_STRIDE + ka);
#pragma unroll
        for (int np = 0; np < NTILES / 2; np++) {
            uint4 bh = ldsm4(wH + (uint32_t)np * 16 * (WKP * 2) + ka);
            uint4 bl = ldsm4(wL + (uint32_t)np * 16 * (WKP * 2) + ka);
            const int nt0 = 2 * np, nt1 = 2 * np + 1;
            mma_bf16(c[0][nt0], ah0, bh.x, bh.y);
            mma_bf16(c[0][nt0], ah0, bl.x, bl.y);
            mma_bf16(c[0][nt0], al0, bh.x, bh.y);
            mma_bf16(c[1][nt0], ah1, bh.x, bh.y);
            mma_bf16(c[1][nt0], ah1, bl.x, bl.y);
            mma_bf16(c[1][nt0], al1, bh.x, bh.y);
            mma_bf16(c[0][nt1], ah0, bh.z, bh.w);
            mma_bf16(c[0][nt1], ah0, bl.z, bl.w);
            mma_bf16(c[0][nt1], al0, bh.z, bh.w);
            mma_bf16(c[1][nt1], ah1, bh.z, bh.w);
            mma_bf16(c[1][nt1], ah1, bl.z, bl.w);
            mma_bf16(c[1][nt1], al1, bh.z, bh.w);
        }
    }
}

// epilogue: bias (+relu), split to bf16 hi/lo, store back into A buffers
template <int NTILES, bool RELU>
__device__ __forceinline__ void epi_to_A(float c[2][NTILES][4], const float* sBias, char* aHi,
                                         char* aLo, int m0, int n0) {
    const int lane = threadIdx.x & 31;
    const int cb = n0 + (lane & 3) * 2;
    const int r0 = m0 + (lane >> 2);
#pragma unroll
    for (int mt = 0; mt < 2; mt++) {
#pragma unroll
        for (int nt = 0; nt < NTILES; nt++) {
            int col = cb + nt * 8;
            float2 bb = *(const float2*)(sBias + col);
            float v0 = c[mt][nt][0] + bb.x, v1 = c[mt][nt][1] + bb.y;
            float v2 = c[mt][nt][2] + bb.x, v3 = c[mt][nt][3] + bb.y;
            if (RELU) {
                v0 = fmaxf(v0, 0.f); v1 = fmaxf(v1, 0.f);
                v2 = fmaxf(v2, 0.f); v3 = fmaxf(v3, 0.f);
            }
            int r = r0 + mt * 16;
            uint32_t h, l;
            split2(v0, v1, h, l);
            *(uint32_t*)(aHi + (uint32_t)r * A_STRIDE + col * 2) = h;
            *(uint32_t*)(aLo + (uint32_t)r * A_STRIDE + col * 2) = l;
            split2(v2, v3, h, l);
            *(uint32_t*)(aHi + (uint32_t)(r + 8) * A_STRIDE + col * 2) = h;
            *(uint32_t*)(aLo + (uint32_t)(r + 8) * A_STRIDE + col * 2) = l;
        }
    }
}

// ---------------- weight prep: transpose [k][n]->[n][k], split hi/lo, pad ----------------
__global__ void prep_weights(const float* __restrict__ sW1, const float* __restrict__ sW2,
                             const float* __restrict__ sW3, const float* __restrict__ jW1,
                             const float* __restrict__ jW2, const float* __restrict__ jW3) {
    int idx = blockIdx.x * blockDim.x + threadIdx.x;
    if (idx >= W1_ELEMS + W2_ELEMS + W3_ELEMS) return;
    int mlp = blockIdx.y;
    const float* W;
    int n, k, Kp, Kreal, N, hiE, loE;
    if (idx < W1_ELEMS) {
        Kp = W1_KP; n = idx / Kp; k = idx % Kp; N = 128;
        Kreal = mlp ? 96 : 32;
        W = mlp ? jW1 : sW1;
        hiE = 0; loE = W1_ELEMS;
    } else if (idx < W1_ELEMS + W2_ELEMS) {
        int li = idx - W1_ELEMS;
        Kp = W23_KP; n = li / Kp; k = li % Kp; N = 128;
        Kreal = 128;
        W = mlp ? jW2 : sW2;
        hiE = 2 * W1_ELEMS; loE = 2 * W1_ELEMS + W2_ELEMS;
    } else {
        int li = idx - W1_ELEMS - W2_ELEMS;
        Kp = W23_KP; n = li / Kp; k = li % Kp; N = 32;
        Kreal = 128;
        W = mlp ? jW3 : sW3;
        hiE = 2 * W1_ELEMS + 2 * W2_ELEMS; loE = hiE + W3_ELEMS;
    }
    float w = (k < Kreal) ? W[k * N + n] : 0.f;
    __nv_bfloat16 bh = __float2bfloat16(w);
    float r = w - __bfloat162float(bh);
    __nv_bfloat16 bl = __float2bfloat16(r);
    __nv_bfloat16* base = (__nv_bfloat16*)(g_wstage + (size_t)mlp * STAGE_BYTES);
    base[hiE + n * Kp + k] = bh;
    base[loE + n * Kp + k] = bl;
}

// ---------------- main tile kernel: 2 warp-groups, each a 64-row tile ----------------
template <bool JOIN, int NK1>
__global__ void __launch_bounds__(256, 1)
    mlp3_kernel(const float* __restrict__ feats, int off, int nShift, const float* __restrict__ prev,
                const float* __restrict__ b1, const float* __restrict__ b2,
                const float* __restrict__ b3, float* __restrict__ Y, int numTiles, int mlpIdx) {
    extern __shared__ char sm[];
    float* smF = (float*)sm;

    copy4(smF, (const float*)(g_wstage + (size_t)mlpIdx * STAGE_BYTES), STAGE_BYTES / 4);
    copy4(smF + OFF_BIAS / 4, b1, 128);
    copy4(smF + OFF_BIAS / 4 + 128, b2, 128);
    copy4(smF + OFF_BIAS / 4 + 256, b3, 32);
    __syncthreads();

    const uint32_t su = smem_u32(sm);
    const float* sB1 = smF + OFF_BIAS / 4;
    const float* sB2 = sB1 + 128;
    const float* sB3 = sB2 + 128;

    const int t = threadIdx.x;
    const int grp = t >> 7;        // 0 or 1
    const int tl = t & 127;        // thread within group
    const int wg = tl >> 5;        // warp within group (0..3)
    const int lane = t & 31;

    char* aHi = sm + OFF_A + grp * GRP_A_BYTES;
    char* aLo = aHi + GRP_A_LO;
    const uint32_t aHiU = su + OFF_A + grp * GRP_A_BYTES;
    const uint32_t aLoU = aHiU + GRP_A_LO;

    const int m0 = (wg & 1) * 32;      // rows within the group's 64-row tile
    const int n064 = (wg >> 1) * 64;   // N=128 layers
    const int n016 = (wg >> 1) * 16;   // N=32 layer
    const int arow = tl >> 1;          // assembly: 2 threads per row (64 rows)
    const int ahalf = tl & 1;

    float c[2][8][4];
    float c3[2][2][4];

    for (int tile = blockIdx.x * 2 + grp; tile < numTiles; tile += gridDim.x * 2) {
        // ---- assemble layer-1 input (bf16 hi/lo) ----
        if (JOIN) {
            int g = tile * 64 + arow;
            int bidx = g >> nShift, i = g & ((1 << nShift) - 1);
            const float4* frow =
                (const float4*)(feats + ((size_t)bidx * (NLEAF - 1) + off + i) * 32);
            const float4* crow =
                (const float4*)(prev + (((size_t)bidx << (nShift + 1)) + 2 * (size_t)i) * 32);
            int q0 = ahalf * 12;
#pragma unroll
            for (int jj = 0; jj < 12; jj++) {
                int q = q0 + jj;
                float4 v = (q < 8) ? frow[q] : crow[q - 8];
                store4A(aHi, aLo, arow, q * 4, v);
            }
        } else {
            const float4* xr = (const float4*)(feats + ((size_t)tile * 64 + arow) * 32);
            int q0 = ahalf * 4;
#pragma unroll
            for (int jj = 0; jj < 4; jj++) {
                int q = q0 + jj;
                store4A(aHi, aLo, arow, q * 4, xr[q]);
            }
        }
        bar_grp(grp);

        // ---- layer 1 ----
        layer_mma<NK1, 8, W1_KP>(aHiU, aLoU, su + OFF_W1H, su + OFF_W1L, c, m0, n064);
        bar_grp(grp);
        epi_to_A<8, true>(c, sB1, aHi, aLo, m0, n064);
        bar_grp(grp);

        // ---- layer 2 ----
        layer_mma<8, 8, W23_KP>(aHiU, aLoU, su + OFF_W2H, su + OFF_W2L, c, m0, n064);
        bar_grp(grp);
        epi_to_A<8, true>(c, sB2, aHi, aLo, m0, n064);
        bar_grp(grp);

        // ---- layer 3 (N=32, no relu) -> gmem ----
        layer_mma<8, 2, W23_KP>(aHiU, aLoU, su + OFF_W3H, su + OFF_W3L, c3, m0, n016);
        bar_grp(grp);  // A reads done before next tile's assembly overwrites
        {
            const int cb = n016 + (lane & 3) * 2;
            const int r0 = m0 + (lane >> 2);
#pragma unroll
            for (int mt = 0; mt < 2; mt++) {
#pragma unroll
                for (int nt = 0; nt < 2; nt++) {
                    int col = cb + nt * 8;
                    float2 bb = *(const float2*)(sB3 + col);
                    int r = r0 + mt * 16;
                    float2 o0 = make_float2(c3[mt][nt][0] + bb.x, c3[mt][nt][1] + bb.y);
                    float2 o1 = make_float2(c3[mt][nt][2] + bb.x, c3[mt][nt][3] + bb.y);
                    *(float2*)(Y + ((size_t)tile * 64 + r) * 32 + col) = o0;
                    *(float2*)(Y + ((size_t)tile * 64 + r + 8) * 32 + col) = o1;
                }
            }
        }
    }
}

__global__ void gather_kernel(const float* __restrict__ src, float* __restrict__ out) {
    int b = blockIdx.x * blockDim.x + threadIdx.x;
    if (b < B_DIM) out[b] = src[(size_t)b * 32];
}

extern "C" void kernel_launch(void* const* d_in, const int* in_sizes, int n_in, void* d_out,
                              int out_size) {
    const float* leaf = (const float*)d_in[0];
    const float* internal = (const float*)d_in[1];
    const float* sW1 = (const float*)d_in[2];
    const float* sb1 = (const float*)d_in[3];
    const float* sW2 = (const float*)d_in[4];
    const float* sb2 = (const float*)d_in[5];
    const float* sW3 = (const float*)d_in[6];
    const float* sb3 = (const float*)d_in[7];
    const float* jW1 = (const float*)d_in[8];
    const float* jb1 = (const float*)d_in[9];
    const float* jW2 = (const float*)d_in[10];
    const float* jb2 = (const float*)d_in[11];
    const float* jW3 = (const float*)d_in[12];
    const float* jb3 = (const float*)d_in[13];
    float* out = (float*)d_out;

    float *bufA, *bufB;
    cudaGetSymbolAddress((void**)&bufA, g_bufA);
    cudaGetSymbolAddress((void**)&bufB, g_bufB);

    cudaFuncSetAttribute(mlp3_kernel<false, 2>, cudaFuncAttributeMaxDynamicSharedMemorySize,
                         SM_BYTES);
    cudaFuncSetAttribute(mlp3_kernel<true, 6>, cudaFuncAttributeMaxDynamicSharedMemorySize,
                         SM_BYTES);

    int sms = 148;
    cudaDeviceGetAttribute(&sms, cudaDevAttrMultiProcessorCount, 0);

    const int totalW = W1_ELEMS + W2_ELEMS + W3_ELEMS;
    prep_weights<<<dim3((totalW + 255) / 256, 2), 256>>>(sW1, sW2, sW3, jW1, jW2, jW3);

    // leaf: 2048*1024 rows / 64 = 32768 tiles (2 per CTA per pass)
    mlp3_kernel<false, 2><<<sms, 256, SM_BYTES>>>(leaf, 0, 0, nullptr, sb1, sb2, sb3, bufA, 32768,
                                                  0);

    float* src = bufA;
    float* dst = bufB;
    int off = 0;
    for (int sh = 9; sh >= 0; sh--) {
        int n = 1 << sh;
        int tiles = 32 * n;  // 2048*n/64
        mlp3_kernel<true, 6><<<sms, 256, SM_BYTES>>>(internal, off, sh, src, jb1, jb2, jb3, dst,
                                                     tiles, 1);
        off += n;
        float* tmp = src;
        src = dst;
        dst = tmp;
    }
    gather_kernel<<<(B_DIM + 255) / 256, 256>>>(src, out);
}

// round 14
// speedup vs baseline: 1.2580x; 1.2580x over previous
#include <cuda_runtime.h>
#include <cuda_bf16.h>
#include <cstdint>

#define B_DIM 2048
#define NLEAF 1024

// ---------------- device scratch (no allocations allowed) ----------------
__device__ __align__(256) float g_bufA[(size_t)B_DIM * NLEAF * 32];        // 256 MB
__device__ __align__(256) float g_bufB[(size_t)B_DIM * (NLEAF / 2) * 32];  // 128 MB
// per-MLP weight stage: W1t hi/lo [128][104], W2t hi/lo [128][136], W3t hi/lo [32][136]
#define W1_ELEMS 13312  // 128*104
#define W2_ELEMS 17408  // 128*136
#define W3_ELEMS 4352   // 32*136
#define STAGE_BYTES 140288
__device__ __align__(256) unsigned char g_wstage[2 * STAGE_BYTES];

// ---------------- smem layout (bytes): weights + bias only ----------------
#define OFF_W1H 0
#define OFF_W1L 26624
#define OFF_W2H 53248
#define OFF_W2L 88064
#define OFF_W3H 122880
#define OFF_W3L 131584
#define OFF_BIAS 140288  // b1(128f) b2(128f) b3(32f)
#define SM_BYTES 141440

#define W1_KP 104   // 208B row stride; 208 % 128 = 80 -> conflict-free LDSM
#define W23_KP 136  // 272B row stride; 272 % 128 = 16 -> conflict-free

// ---------------- PTX helpers (base-arch only: ldmatrix + mma.sync) ----------------
__device__ __forceinline__ uint32_t smem_u32(const void* p) {
    uint32_t a;
    asm("{ .reg .u64 t; cvta.to.shared.u64 t, %1; cvt.u32.u64 %0, t; }" : "=r"(a) : "l"(p));
    return a;
}
__device__ __forceinline__ uint4 ldsm4(uint32_t a) {
    uint4 r;
    asm volatile("ldmatrix.sync.aligned.m8n8.x4.shared.b16 {%0,%1,%2,%3}, [%4];"
                 : "=r"(r.x), "=r"(r.y), "=r"(r.z), "=r"(r.w)
                 : "r"(a));
    return r;
}
__device__ __forceinline__ void mma_bf16(float* c, const uint4& a, uint32_t b0, uint32_t b1) {
    asm volatile(
        "mma.sync.aligned.m16n8k16.row.col.f32.bf16.bf16.f32 "
        "{%0,%1,%2,%3}, {%4,%5,%6,%7}, {%8,%9}, {%0,%1,%2,%3};"
        : "+f"(c[0]), "+f"(c[1]), "+f"(c[2]), "+f"(c[3])
        : "r"(a.x), "r"(a.y), "r"(a.z), "r"(a.w), "r"(b0), "r"(b1));
}

// ---------------- bf16 hi/lo split ----------------
__device__ __forceinline__ void split2(float x, float y, uint32_t& h, uint32_t& l) {
    __nv_bfloat16 hx = __float2bfloat16(x), hy = __float2bfloat16(y);
    float rx = x - __bfloat162float(hx), ry = y - __bfloat162float(hy);
    __nv_bfloat16 lx = __float2bfloat16(rx), ly = __float2bfloat16(ry);
    h = (uint32_t)__bfloat16_as_ushort(hx) | ((uint32_t)__bfloat16_as_ushort(hy) << 16);
    l = (uint32_t)__bfloat16_as_ushort(lx) | ((uint32_t)__bfloat16_as_ushort(ly) << 16);
}

__device__ __forceinline__ void copy4(float* dst, const float* __restrict__ src, int nfloats) {
    const float4* s = (const float4*)src;
    float4* d = (float4*)dst;
    int n4 = nfloats >> 2;
    for (int i = threadIdx.x; i < n4; i += blockDim.x) d[i] = s[i];
}

// ---------------- W block: one k-step across NP2*2 n-tiles, 3-term split ----------------
template <int NP2, int WKP>
__device__ __forceinline__ void wblock(uint32_t wH, uint32_t wL, uint32_t ka, const uint4 ahi,
                                       const uint4 alo, float (*c)[4]) {
#pragma unroll
    for (int np = 0; np < NP2; np++) {
        uint4 bh = ldsm4(wH + (uint32_t)np * 16 * (WKP * 2) + ka);
        uint4 bl = ldsm4(wL + (uint32_t)np * 16 * (WKP * 2) + ka);
        float* c0 = c[2 * np];
        float* c1 = c[2 * np + 1];
        mma_bf16(c0, ahi, bh.x, bh.y);
        mma_bf16(c0, ahi, bl.x, bl.y);
        mma_bf16(c0, alo, bh.x, bh.y);
        mma_bf16(c1, ahi, bh.z, bh.w);
        mma_bf16(c1, ahi, bl.z, bl.w);
        mma_bf16(c1, alo, bh.z, bh.w);
    }
}

// convert two C tiles (cols 16ks..16ks+15) -> next-layer A fragment (bias+relu+split)
__device__ __forceinline__ void conv2(const float* cA, const float* cB, const float* sBias, int ks,
                                      int cl, uint4& ahi, uint4& alo) {
    float2 b0 = *(const float2*)(sBias + 16 * ks + cl);
    float2 b1 = *(const float2*)(sBias + 16 * ks + 8 + cl);
    float v0 = fmaxf(cA[0] + b0.x, 0.f), v1 = fmaxf(cA[1] + b0.y, 0.f);
    float v2 = fmaxf(cA[2] + b0.x, 0.f), v3 = fmaxf(cA[3] + b0.y, 0.f);
    float u0 = fmaxf(cB[0] + b1.x, 0.f), u1 = fmaxf(cB[1] + b1.y, 0.f);
    float u2 = fmaxf(cB[2] + b1.x, 0.f), u3 = fmaxf(cB[3] + b1.y, 0.f);
    split2(v0, v1, ahi.x, alo.x);
    split2(v2, v3, ahi.y, alo.y);
    split2(u0, u1, ahi.z, alo.z);
    split2(u2, u3, ahi.w, alo.w);
}

// build A fragment from two gmem float rows (k-pair at kc, kc+8)
__device__ __forceinline__ void gfrag(const float* rlo_k, const float* rhi_k,
                                      const float* rlo_k8, const float* rhi_k8, uint4& ahi,
                                      uint4& alo) {
    float2 p0 = *(const float2*)rlo_k;
    float2 p1 = *(const float2*)rhi_k;
    float2 p2 = *(const float2*)rlo_k8;
    float2 p3 = *(const float2*)rhi_k8;
    split2(p0.x, p0.y, ahi.x, alo.x);
    split2(p1.x, p1.y, ahi.y, alo.y);
    split2(p2.x, p2.y, ahi.z, alo.z);
    split2(p3.x, p3.y, ahi.w, alo.w);
}

// ---------------- weight prep: transpose [k][n]->[n][k], split hi/lo, pad ----------------
__global__ void prep_weights(const float* __restrict__ sW1, const float* __restrict__ sW2,
                             const float* __restrict__ sW3, const float* __restrict__ jW1,
                             const float* __restrict__ jW2, const float* __restrict__ jW3) {
    int idx = blockIdx.x * blockDim.x + threadIdx.x;
    if (idx >= W1_ELEMS + W2_ELEMS + W3_ELEMS) return;
    int mlp = blockIdx.y;
    const float* W;
    int n, k, Kp, Kreal, N, hiE, loE;
    if (idx < W1_ELEMS) {
        Kp = W1_KP; n = idx / Kp; k = idx % Kp; N = 128;
        Kreal = mlp ? 96 : 32;
        W = mlp ? jW1 : sW1;
        hiE = 0; loE = W1_ELEMS;
    } else if (idx < W1_ELEMS + W2_ELEMS) {
        int li = idx - W1_ELEMS;
        Kp = W23_KP; n = li / Kp; k = li % Kp; N = 128;
        Kreal = 128;
        W = mlp ? jW2 : sW2;
        hiE = 2 * W1_ELEMS; loE = 2 * W1_ELEMS + W2_ELEMS;
    } else {
        int li = idx - W1_ELEMS - W2_ELEMS;
        Kp = W23_KP; n = li / Kp; k = li % Kp; N = 32;
        Kreal = 128;
        W = mlp ? jW3 : sW3;
        hiE = 2 * W1_ELEMS + 2 * W2_ELEMS; loE = hiE + W3_ELEMS;
    }
    float w = (k < Kreal) ? W[k * N + n] : 0.f;
    __nv_bfloat16 bh = __float2bfloat16(w);
    float r = w - __bfloat162float(bh);
    __nv_bfloat16 bl = __float2bfloat16(r);
    __nv_bfloat16* base = (__nv_bfloat16*)(g_wstage + (size_t)mlp * STAGE_BYTES);
    base[hiE + n * Kp + k] = bh;
    base[loE + n * Kp + k] = bl;
}

// ---------------- main kernel: 8 warps x 16 rows = 128-row tiles, zero barriers ----------------
template <bool JOIN>
__global__ void __launch_bounds__(256, 1)
    mlp3_kernel(const float* __restrict__ feats, int off, int nShift, const float* __restrict__ prev,
                const float* __restrict__ b1, const float* __restrict__ b2,
                const float* __restrict__ b3, float* __restrict__ Y, int numTiles, int mlpIdx) {
    extern __shared__ char sm[];
    float* smF = (float*)sm;
    copy4(smF, (const float*)(g_wstage + (size_t)mlpIdx * STAGE_BYTES), STAGE_BYTES / 4);
    copy4(smF + OFF_BIAS / 4, b1, 128);
    copy4(smF + OFF_BIAS / 4 + 128, b2, 128);
    copy4(smF + OFF_BIAS / 4 + 256, b3, 32);
    __syncthreads();

    const uint32_t su = smem_u32(sm);
    const float* sB1 = smF + OFF_BIAS / 4;
    const float* sB2 = sB1 + 128;
    const float* sB3 = sB2 + 128;

    const int t = threadIdx.x;
    const int w = t >> 5;
    const int lane = t & 31;
    const int cl = (lane & 3) * 2;

    // ldsm lane->address mapping for W tiles (row starts of 8x8 tiles)
    const uint32_t wo1 = (uint32_t)((lane & 7) + ((lane >> 4) << 3)) * (W1_KP * 2) +
                         (uint32_t)(((lane >> 3) & 1) << 4);
    const uint32_t wo23 = (uint32_t)((lane & 7) + ((lane >> 4) << 3)) * (W23_KP * 2) +
                          (uint32_t)(((lane >> 3) & 1) << 4);
    const uint32_t wH1 = su + OFF_W1H + wo1, wL1 = su + OFF_W1L + wo1;
    const uint32_t wH2 = su + OFF_W2H + wo23, wL2 = su + OFF_W2L + wo23;
    const uint32_t wH3 = su + OFF_W3H + wo23, wL3 = su + OFF_W3L + wo23;

    for (int tile = blockIdx.x; tile < numTiles; tile += gridDim.x) {
        const int g0 = tile * 128 + w * 16 + (lane >> 2);  // row lo
        const int g1 = g0 + 8;                             // row hi

        float c1[16][4];
#pragma unroll
        for (int i = 0; i < 16; i++)
#pragma unroll
            for (int j = 0; j < 4; j++) c1[i][j] = 0.f;

        // ---- layer 1: A fragments straight from gmem ----
        if (JOIN) {
            const int mask = (1 << nShift) - 1;
            const int b0i = g0 >> nShift, i0 = g0 & mask;
            const int b1i = g1 >> nShift, i1 = g1 & mask;
            const float* f0 = feats + ((size_t)b0i * (NLEAF - 1) + off + i0) * 32;
            const float* f1 = feats + ((size_t)b1i * (NLEAF - 1) + off + i1) * 32;
            const float* cA0 = prev + (((size_t)b0i << (nShift + 1)) + 2 * (size_t)i0) * 32;
            const float* cA1 = prev + (((size_t)b1i << (nShift + 1)) + 2 * (size_t)i1) * 32;
            const float* cB0 = cA0 + 32;
            const float* cB1 = cA1 + 32;
            uint4 ahi, alo;
            // ks0: cols [0,15] feats ; ks1: [16,31] feats
            gfrag(f0 + cl, f1 + cl, f0 + cl + 8, f1 + cl + 8, ahi, alo);
            wblock<8, W1_KP>(wH1, wL1, 0, ahi, alo, c1);
            gfrag(f0 + cl + 16, f1 + cl + 16, f0 + cl + 24, f1 + cl + 24, ahi, alo);
            wblock<8, W1_KP>(wH1, wL1, 32, ahi, alo, c1);
            // ks2,3: cols [32,63] -> child0
            gfrag(cA0 + cl, cA1 + cl, cA0 + cl + 8, cA1 + cl + 8, ahi, alo);
            wblock<8, W1_KP>(wH1, wL1, 64, ahi, alo, c1);
            gfrag(cA0 + cl + 16, cA1 + cl + 16, cA0 + cl + 24, cA1 + cl + 24, ahi, alo);
            wblock<8, W1_KP>(wH1, wL1, 96, ahi, alo, c1);
            // ks4,5: cols [64,95] -> child1
            gfrag(cB0 + cl, cB1 + cl, cB0 + cl + 8, cB1 + cl + 8, ahi, alo);
            wblock<8, W1_KP>(wH1, wL1, 128, ahi, alo, c1);
            gfrag(cB0 + cl + 16, cB1 + cl + 16, cB0 + cl + 24, cB1 + cl + 24, ahi, alo);
            wblock<8, W1_KP>(wH1, wL1, 160, ahi, alo, c1);
        } else {
            const float* f0 = feats + (size_t)g0 * 32;
            const float* f1 = feats + (size_t)g1 * 32;
            uint4 ahi, alo;
            gfrag(f0 + cl, f1 + cl, f0 + cl + 8, f1 + cl + 8, ahi, alo);
            wblock<8, W1_KP>(wH1, wL1, 0, ahi, alo, c1);
            gfrag(f0 + cl + 16, f1 + cl + 16, f0 + cl + 24, f1 + cl + 24, ahi, alo);
            wblock<8, W1_KP>(wH1, wL1, 32, ahi, alo, c1);
        }

        // ---- layer 2: A from c1 registers ----
        float c2[16][4];
#pragma unroll
        for (int i = 0; i < 16; i++)
#pragma unroll
            for (int j = 0; j < 4; j++) c2[i][j] = 0.f;
#pragma unroll
        for (int ks = 0; ks < 8; ks++) {
            uint4 ahi, alo;
            conv2(c1[2 * ks], c1[2 * ks + 1], sB1, ks, cl, ahi, alo);
            wblock<8, W23_KP>(wH2, wL2, (uint32_t)ks * 32, ahi, alo, c2);
        }

        // ---- layer 3 (N=32): A from c2 registers ----
        float c3[4][4];
#pragma unroll
        for (int i = 0; i < 4; i++)
#pragma unroll
            for (int j = 0; j < 4; j++) c3[i][j] = 0.f;
#pragma unroll
        for (int ks = 0; ks < 8; ks++) {
            uint4 ahi, alo;
            conv2(c2[2 * ks], c2[2 * ks + 1], sB2, ks, cl, ahi, alo);
            wblock<2, W23_KP>(wH3, wL3, (uint32_t)ks * 32, ahi, alo, c3);
        }

        // ---- output: bias3, no relu ----
        float* o0 = Y + (size_t)g0 * 32;
        float* o1 = Y + (size_t)g1 * 32;
#pragma unroll
        for (int nt = 0; nt < 4; nt++) {
            float2 bb = *(const float2*)(sB3 + nt * 8 + cl);
            *(float2*)(o0 + nt * 8 + cl) = make_float2(c3[nt][0] + bb.x, c3[nt][1] + bb.y);
            *(float2*)(o1 + nt * 8 + cl) = make_float2(c3[nt][2] + bb.x, c3[nt][3] + bb.y);
        }
    }
}

__global__ void gather_kernel(const float* __restrict__ src, float* __restrict__ out) {
    int b = blockIdx.x * blockDim.x + threadIdx.x;
    if (b < B_DIM) out[b] = src[(size_t)b * 32];
}

extern "C" void kernel_launch(void* const* d_in, const int* in_sizes, int n_in, void* d_out,
                              int out_size) {
    const float* leaf = (const float*)d_in[0];
    const float* internal = (const float*)d_in[1];
    const float* sW1 = (const float*)d_in[2];
    const float* sb1 = (const float*)d_in[3];
    const float* sW2 = (const float*)d_in[4];
    const float* sb2 = (const float*)d_in[5];
    const float* sW3 = (const float*)d_in[6];
    const float* sb3 = (const float*)d_in[7];
    const float* jW1 = (const float*)d_in[8];
    const float* jb1 = (const float*)d_in[9];
    const float* jW2 = (const float*)d_in[10];
    const float* jb2 = (const float*)d_in[11];
    const float* jW3 = (const float*)d_in[12];
    const float* jb3 = (const float*)d_in[13];
    float* out = (float*)d_out;

    float *bufA, *bufB;
    cudaGetSymbolAddress((void**)&bufA, g_bufA);
    cudaGetSymbolAddress((void**)&bufB, g_bufB);

    cudaFuncSetAttribute(mlp3_kernel<false>, cudaFuncAttributeMaxDynamicSharedMemorySize,
                         SM_BYTES);
    cudaFuncSetAttribute(mlp3_kernel<true>, cudaFuncAttributeMaxDynamicSharedMemorySize,
                         SM_BYTES);

    int sms = 148;
    cudaDeviceGetAttribute(&sms, cudaDevAttrMultiProcessorCount, 0);

    const int totalW = W1_ELEMS + W2_ELEMS + W3_ELEMS;
    prep_weights<<<dim3((totalW + 255) / 256, 2), 256>>>(sW1, sW2, sW3, jW1, jW2, jW3);

    // leaf: 2048*1024 rows / 128 = 16384 tiles
    mlp3_kernel<false><<<sms, 256, SM_BYTES>>>(leaf, 0, 0, nullptr, sb1, sb2, sb3, bufA, 16384, 0);

    float* src = bufA;
    float* dst = bufB;
    int off = 0;
    for (int sh = 9; sh >= 0; sh--) {
        int n = 1 << sh;
        int tiles = 16 * n;  // 2048*n/128
        mlp3_kernel<true><<<sms, 256, SM_BYTES>>>(internal, off, sh, src, jb1, jb2, jb3, dst,
                                                  tiles, 1);
        off += n;
        float* tmp = src;
        src = dst;
        dst = tmp;
    }
    gather_kernel<<<(B_DIM + 255) / 256, 256>>>(src, out);
}

// round 15
// speedup vs baseline: 1.3650x; 1.0851x over previous
#include <cuda_runtime.h>
#include <cuda_bf16.h>
#include <cstdint>

#define B_DIM 2048
#define NLEAF 1024

// ---------------- device scratch (no allocations allowed) ----------------
__device__ __align__(256) float g_bufA[(size_t)B_DIM * NLEAF * 32];        // 256 MB
__device__ __align__(256) float g_bufB[(size_t)B_DIM * (NLEAF / 2) * 32];  // 128 MB
// per-MLP weight stage: W1t hi/lo [128][104], W2t hi/lo [128][136], W3t hi/lo [32][136]
#define W1_ELEMS 13312  // 128*104
#define W2_ELEMS 17408  // 128*136
#define W3_ELEMS 4352   // 32*136
#define STAGE_BYTES 140288
__device__ __align__(256) unsigned char g_wstage[2 * STAGE_BYTES];

// ---------------- smem layout (bytes): weights + bias only ----------------
#define OFF_W1H 0
#define OFF_W1L 26624
#define OFF_W2H 53248
#define OFF_W2L 88064
#define OFF_W3H 122880
#define OFF_W3L 131584
#define OFF_BIAS 140288  // b1(128f) b2(128f) b3(32f)
#define SM_BYTES 141440

#define W1_KP 104   // 208B row stride; 208 % 128 = 80 -> conflict-free LDSM
#define W23_KP 136  // 272B row stride; 272 % 128 = 16 -> conflict-free

// ---------------- PTX helpers (base-arch only: ldmatrix + mma.sync) ----------------
__device__ __forceinline__ uint32_t smem_u32(const void* p) {
    uint32_t a;
    asm("{ .reg .u64 t; cvta.to.shared.u64 t, %1; cvt.u32.u64 %0, t; }" : "=r"(a) : "l"(p));
    return a;
}
__device__ __forceinline__ uint4 ldsm4(uint32_t a) {
    uint4 r;
    asm volatile("ldmatrix.sync.aligned.m8n8.x4.shared.b16 {%0,%1,%2,%3}, [%4];"
                 : "=r"(r.x), "=r"(r.y), "=r"(r.z), "=r"(r.w)
                 : "r"(a));
    return r;
}
__device__ __forceinline__ void mma_bf16(float* c, const uint4& a, uint32_t b0, uint32_t b1) {
    asm volatile(
        "mma.sync.aligned.m16n8k16.row.col.f32.bf16.bf16.f32 "
        "{%0,%1,%2,%3}, {%4,%5,%6,%7}, {%8,%9}, {%0,%1,%2,%3};"
        : "+f"(c[0]), "+f"(c[1]), "+f"(c[2]), "+f"(c[3])
        : "r"(a.x), "r"(a.y), "r"(a.z), "r"(a.w), "r"(b0), "r"(b1));
}

// ---------------- bf16 hi/lo split ----------------
__device__ __forceinline__ void split2(float x, float y, uint32_t& h, uint32_t& l) {
    __nv_bfloat16 hx = __float2bfloat16(x), hy = __float2bfloat16(y);
    float rx = x - __bfloat162float(hx), ry = y - __bfloat162float(hy);
    __nv_bfloat16 lx = __float2bfloat16(rx), ly = __float2bfloat16(ry);
    h = (uint32_t)__bfloat16_as_ushort(hx) | ((uint32_t)__bfloat16_as_ushort(hy) << 16);
    l = (uint32_t)__bfloat16_as_ushort(lx) | ((uint32_t)__bfloat16_as_ushort(ly) << 16);
}

__device__ __forceinline__ void copy4(float* dst, const float* __restrict__ src, int nfloats) {
    const float4* s = (const float4*)src;
    float4* d = (float4*)dst;
    int n4 = nfloats >> 2;
    for (int i = threadIdx.x; i < n4; i += blockDim.x) d[i] = s[i];
}

// ---------------- W block: one k-step across NP2*2 n-tiles, 3-term split ----------------
// bh consumers issued before bl consumers (extra LDSM dep slack for bl);
// per-accumulator MMA order preserved (bit-identical fp32 accumulation).
template <int NP2, int WKP>
__device__ __forceinline__ void wblock(uint32_t wH, uint32_t wL, uint32_t ka, const uint4 ahi,
                                       const uint4 alo, float (*c)[4]) {
#pragma unroll
    for (int np = 0; np < NP2; np++) {
        uint4 bh = ldsm4(wH + (uint32_t)np * 16 * (WKP * 2) + ka);
        uint4 bl = ldsm4(wL + (uint32_t)np * 16 * (WKP * 2) + ka);
        float* c0 = c[2 * np];
        float* c1 = c[2 * np + 1];
        mma_bf16(c0, ahi, bh.x, bh.y);
        mma_bf16(c1, ahi, bh.z, bh.w);
        mma_bf16(c0, ahi, bl.x, bl.y);
        mma_bf16(c1, ahi, bl.z, bl.w);
        mma_bf16(c0, alo, bh.x, bh.y);
        mma_bf16(c1, alo, bh.z, bh.w);
    }
}

// convert two C tiles (cols 16ks..16ks+15) -> next-layer A fragment (bias+relu+split)
__device__ __forceinline__ void conv2(const float* cA, const float* cB, const float* sBias, int ks,
                                      int cl, uint4& ahi, uint4& alo) {
    float2 b0 = *(const float2*)(sBias + 16 * ks + cl);
    float2 b1 = *(const float2*)(sBias + 16 * ks + 8 + cl);
    float v0 = fmaxf(cA[0] + b0.x, 0.f), v1 = fmaxf(cA[1] + b0.y, 0.f);
    float v2 = fmaxf(cA[2] + b0.x, 0.f), v3 = fmaxf(cA[3] + b0.y, 0.f);
    float u0 = fmaxf(cB[0] + b1.x, 0.f), u1 = fmaxf(cB[1] + b1.y, 0.f);
    float u2 = fmaxf(cB[2] + b1.x, 0.f), u3 = fmaxf(cB[3] + b1.y, 0.f);
    split2(v0, v1, ahi.x, alo.x);
    split2(v2, v3, ahi.y, alo.y);
    split2(u0, u1, ahi.z, alo.z);
    split2(u2, u3, ahi.w, alo.w);
}

// build A fragment from 4 prefetched float2 (row-lo k, row-hi k, row-lo k+8, row-hi k+8)
__device__ __forceinline__ void gfrag_v(float2 p0, float2 p1, float2 p2, float2 p3, uint4& ahi,
                                        uint4& alo) {
    split2(p0.x, p0.y, ahi.x, alo.x);
    split2(p1.x, p1.y, ahi.y, alo.y);
    split2(p2.x, p2.y, ahi.z, alo.z);
    split2(p3.x, p3.y, ahi.w, alo.w);
}

// prefetch one tile's inputs into registers (JOIN: 24 float2, leaf: 8 float2)
template <bool JOIN>
__device__ __forceinline__ void load_inputs(const float* __restrict__ feats,
                                            const float* __restrict__ prev, int off, int nShift,
                                            int tile, int rowIdx, int cl, float2* pf) {
    const int g0 = tile * 128 + rowIdx;
    const int g1 = g0 + 8;
    if (JOIN) {
        const int mask = (1 << nShift) - 1;
        const int b0i = g0 >> nShift, i0 = g0 & mask;
        const int b1i = g1 >> nShift, i1 = g1 & mask;
        const float* f0 = feats + ((size_t)b0i * (NLEAF - 1) + off + i0) * 32;
        const float* f1 = feats + ((size_t)b1i * (NLEAF - 1) + off + i1) * 32;
        const float* cA0 = prev + (((size_t)b0i << (nShift + 1)) + 2 * (size_t)i0) * 32;
        const float* cA1 = prev + (((size_t)b1i << (nShift + 1)) + 2 * (size_t)i1) * 32;
        const float* cB0 = cA0 + 32;
        const float* cB1 = cA1 + 32;
        pf[0] = *(const float2*)(f0 + cl);
        pf[1] = *(const float2*)(f1 + cl);
        pf[2] = *(const float2*)(f0 + cl + 8);
        pf[3] = *(const float2*)(f1 + cl + 8);
        pf[4] = *(const float2*)(f0 + cl + 16);
        pf[5] = *(const float2*)(f1 + cl + 16);
        pf[6] = *(const float2*)(f0 + cl + 24);
        pf[7] = *(const float2*)(f1 + cl + 24);
        pf[8] = *(const float2*)(cA0 + cl);
        pf[9] = *(const float2*)(cA1 + cl);
        pf[10] = *(const float2*)(cA0 + cl + 8);
        pf[11] = *(const float2*)(cA1 + cl + 8);
        pf[12] = *(const float2*)(cA0 + cl + 16);
        pf[13] = *(const float2*)(cA1 + cl + 16);
        pf[14] = *(const float2*)(cA0 + cl + 24);
        pf[15] = *(const float2*)(cA1 + cl + 24);
        pf[16] = *(const float2*)(cB0 + cl);
        pf[17] = *(const float2*)(cB1 + cl);
        pf[18] = *(const float2*)(cB0 + cl + 8);
        pf[19] = *(const float2*)(cB1 + cl + 8);
        pf[20] = *(const float2*)(cB0 + cl + 16);
        pf[21] = *(const float2*)(cB1 + cl + 16);
        pf[22] = *(const float2*)(cB0 + cl + 24);
        pf[23] = *(const float2*)(cB1 + cl + 24);
    } else {
        const float* f0 = feats + (size_t)g0 * 32;
        const float* f1 = feats + (size_t)g1 * 32;
        pf[0] = *(const float2*)(f0 + cl);
        pf[1] = *(const float2*)(f1 + cl);
        pf[2] = *(const float2*)(f0 + cl + 8);
        pf[3] = *(const float2*)(f1 + cl + 8);
        pf[4] = *(const float2*)(f0 + cl + 16);
        pf[5] = *(const float2*)(f1 + cl + 16);
        pf[6] = *(const float2*)(f0 + cl + 24);
        pf[7] = *(const float2*)(f1 + cl + 24);
    }
}

// ---------------- weight prep: transpose [k][n]->[n][k], split hi/lo, pad ----------------
__global__ void prep_weights(const float* __restrict__ sW1, const float* __restrict__ sW2,
                             const float* __restrict__ sW3, const float* __restrict__ jW1,
                             const float* __restrict__ jW2, const float* __restrict__ jW3) {
    int idx = blockIdx.x * blockDim.x + threadIdx.x;
    if (idx >= W1_ELEMS + W2_ELEMS + W3_ELEMS) return;
    int mlp = blockIdx.y;
    const float* W;
    int n, k, Kp, Kreal, N, hiE, loE;
    if (idx < W1_ELEMS) {
        Kp = W1_KP; n = idx / Kp; k = idx % Kp; N = 128;
        Kreal = mlp ? 96 : 32;
        W = mlp ? jW1 : sW1;
        hiE = 0; loE = W1_ELEMS;
    } else if (idx < W1_ELEMS + W2_ELEMS) {
        int li = idx - W1_ELEMS;
        Kp = W23_KP; n = li / Kp; k = li % Kp; N = 128;
        Kreal = 128;
        W = mlp ? jW2 : sW2;
        hiE = 2 * W1_ELEMS; loE = 2 * W1_ELEMS + W2_ELEMS;
    } else {
        int li = idx - W1_ELEMS - W2_ELEMS;
        Kp = W23_KP; n = li / Kp; k = li % Kp; N = 32;
        Kreal = 128;
        W = mlp ? jW3 : sW3;
        hiE = 2 * W1_ELEMS + 2 * W2_ELEMS; loE = hiE + W3_ELEMS;
    }
    float w = (k < Kreal) ? W[k * N + n] : 0.f;
    __nv_bfloat16 bh = __float2bfloat16(w);
    float r = w - __bfloat162float(bh);
    __nv_bfloat16 bl = __float2bfloat16(r);
    __nv_bfloat16* base = (__nv_bfloat16*)(g_wstage + (size_t)mlp * STAGE_BYTES);
    base[hiE + n * Kp + k] = bh;
    base[loE + n * Kp + k] = bl;
}

// ---------------- main kernel: 8 warps x 16 rows, zero barriers, input prefetch ----------------
template <bool JOIN>
__global__ void __launch_bounds__(256, 1)
    mlp3_kernel(const float* __restrict__ feats, int off, int nShift, const float* __restrict__ prev,
                const float* __restrict__ b1, const float* __restrict__ b2,
                const float* __restrict__ b3, float* __restrict__ Y, int numTiles, int mlpIdx) {
    extern __shared__ char sm[];
    float* smF = (float*)sm;
    copy4(smF, (const float*)(g_wstage + (size_t)mlpIdx * STAGE_BYTES), STAGE_BYTES / 4);
    copy4(smF + OFF_BIAS / 4, b1, 128);
    copy4(smF + OFF_BIAS / 4 + 128, b2, 128);
    copy4(smF + OFF_BIAS / 4 + 256, b3, 32);
    __syncthreads();

    const uint32_t su = smem_u32(sm);
    const float* sB1 = smF + OFF_BIAS / 4;
    const float* sB2 = sB1 + 128;
    const float* sB3 = sB2 + 128;

    const int t = threadIdx.x;
    const int w = t >> 5;
    const int lane = t & 31;
    const int cl = (lane & 3) * 2;
    const int rowIdx = w * 16 + (lane >> 2);

    const uint32_t wo1 = (uint32_t)((lane & 7) + ((lane >> 4) << 3)) * (W1_KP * 2) +
                         (uint32_t)(((lane >> 3) & 1) << 4);
    const uint32_t wo23 = (uint32_t)((lane & 7) + ((lane >> 4) << 3)) * (W23_KP * 2) +
                          (uint32_t)(((lane >> 3) & 1) << 4);
    const uint32_t wH1 = su + OFF_W1H + wo1, wL1 = su + OFF_W1L + wo1;
    const uint32_t wH2 = su + OFF_W2H + wo23, wL2 = su + OFF_W2L + wo23;
    const uint32_t wH3 = su + OFF_W3H + wo23, wL3 = su + OFF_W3L + wo23;

    float2 pf[JOIN ? 24 : 8];
    int tile = blockIdx.x;
    if (tile < numTiles) load_inputs<JOIN>(feats, prev, off, nShift, tile, rowIdx, cl, pf);

    for (; tile < numTiles; tile += gridDim.x) {
        const int g0 = tile * 128 + rowIdx;
        const int g1 = g0 + 8;

        float c1[16][4];
#pragma unroll
        for (int i = 0; i < 16; i++)
#pragma unroll
            for (int j = 0; j < 4; j++) c1[i][j] = 0.f;

        // ---- layer 1 from prefetched registers ----
        {
            uint4 ahi, alo;
            gfrag_v(pf[0], pf[1], pf[2], pf[3], ahi, alo);
            wblock<8, W1_KP>(wH1, wL1, 0, ahi, alo, c1);
            gfrag_v(pf[4], pf[5], pf[6], pf[7], ahi, alo);
            wblock<8, W1_KP>(wH1, wL1, 32, ahi, alo, c1);
            if (JOIN) {
                gfrag_v(pf[8], pf[9], pf[10], pf[11], ahi, alo);
                wblock<8, W1_KP>(wH1, wL1, 64, ahi, alo, c1);
                gfrag_v(pf[12], pf[13], pf[14], pf[15], ahi, alo);
                wblock<8, W1_KP>(wH1, wL1, 96, ahi, alo, c1);
                gfrag_v(pf[16], pf[17], pf[18], pf[19], ahi, alo);
                wblock<8, W1_KP>(wH1, wL1, 128, ahi, alo, c1);
                gfrag_v(pf[20], pf[21], pf[22], pf[23], ahi, alo);
                wblock<8, W1_KP>(wH1, wL1, 160, ahi, alo, c1);
            }
        }

        // ---- prefetch next tile's inputs (covered by layers 2+3) ----
        {
            int nt = tile + gridDim.x;
            int pt = (nt < numTiles) ? nt : tile;
            load_inputs<JOIN>(feats, prev, off, nShift, pt, rowIdx, cl, pf);
        }

        // ---- layer 2: A from c1 registers ----
        float c2[16][4];
#pragma unroll
        for (int i = 0; i < 16; i++)
#pragma unroll
            for (int j = 0; j < 4; j++) c2[i][j] = 0.f;
#pragma unroll
        for (int ks = 0; ks < 8; ks++) {
            uint4 ahi, alo;
            conv2(c1[2 * ks], c1[2 * ks + 1], sB1, ks, cl, ahi, alo);
            wblock<8, W23_KP>(wH2, wL2, (uint32_t)ks * 32, ahi, alo, c2);
        }

        // ---- layer 3 (N=32): A from c2 registers ----
        float c3[4][4];
#pragma unroll
        for (int i = 0; i < 4; i++)
#pragma unroll
            for (int j = 0; j < 4; j++) c3[i][j] = 0.f;
#pragma unroll
        for (int ks = 0; ks < 8; ks++) {
            uint4 ahi, alo;
            conv2(c2[2 * ks], c2[2 * ks + 1], sB2, ks, cl, ahi, alo);
            wblock<2, W23_KP>(wH3, wL3, (uint32_t)ks * 32, ahi, alo, c3);
        }

        // ---- output: bias3, no relu ----
        float* o0 = Y + (size_t)g0 * 32;
        float* o1 = Y + (size_t)g1 * 32;
#pragma unroll
        for (int nt = 0; nt < 4; nt++) {
            float2 bb = *(const float2*)(sB3 + nt * 8 + cl);
            *(float2*)(o0 + nt * 8 + cl) = make_float2(c3[nt][0] + bb.x, c3[nt][1] + bb.y);
            *(float2*)(o1 + nt * 8 + cl) = make_float2(c3[nt][2] + bb.x, c3[nt][3] + bb.y);
        }
    }
}

__global__ void gather_kernel(const float* __restrict__ src, float* __restrict__ out) {
    int b = blockIdx.x * blockDim.x + threadIdx.x;
    if (b < B_DIM) out[b] = src[(size_t)b * 32];
}

extern "C" void kernel_launch(void* const* d_in, const int* in_sizes, int n_in, void* d_out,
                              int out_size) {
    const float* leaf = (const float*)d_in[0];
    const float* internal = (const float*)d_in[1];
    const float* sW1 = (const float*)d_in[2];
    const float* sb1 = (const float*)d_in[3];
    const float* sW2 = (const float*)d_in[4];
    const float* sb2 = (const float*)d_in[5];
    const float* sW3 = (const float*)d_in[6];
    const float* sb3 = (const float*)d_in[7];
    const float* jW1 = (const float*)d_in[8];
    const float* jb1 = (const float*)d_in[9];
    const float* jW2 = (const float*)d_in[10];
    const float* jb2 = (const float*)d_in[11];
    const float* jW3 = (const float*)d_in[12];
    const float* jb3 = (const float*)d_in[13];
    float* out = (float*)d_out;

    float *bufA, *bufB;
    cudaGetSymbolAddress((void**)&bufA, g_bufA);
    cudaGetSymbolAddress((void**)&bufB, g_bufB);

    cudaFuncSetAttribute(mlp3_kernel<false>, cudaFuncAttributeMaxDynamicSharedMemorySize,
                         SM_BYTES);
    cudaFuncSetAttribute(mlp3_kernel<true>, cudaFuncAttributeMaxDynamicSharedMemorySize,
                         SM_BYTES);

    int sms = 148;
    cudaDeviceGetAttribute(&sms, cudaDevAttrMultiProcessorCount, 0);

    const int totalW = W1_ELEMS + W2_ELEMS + W3_ELEMS;
    prep_weights<<<dim3((totalW + 255) / 256, 2), 256>>>(sW1, sW2, sW3, jW1, jW2, jW3);

    // leaf: 2048*1024 rows / 128 = 16384 tiles
    mlp3_kernel<false><<<sms, 256, SM_BYTES>>>(leaf, 0, 0, nullptr, sb1, sb2, sb3, bufA, 16384, 0);

    float* src = bufA;
    float* dst = bufB;
    int off = 0;
    for (int sh = 9; sh >= 0; sh--) {
        int n = 1 << sh;
        int tiles = 16 * n;  // 2048*n/128
        mlp3_kernel<true><<<sms, 256, SM_BYTES>>>(internal, off, sh, src, jb1, jb2, jb3, dst,
                                                  tiles, 1);
        off += n;
        float* tmp = src;
        src = dst;
        dst = tmp;
    }
    gather_kernel<<<(B_DIM + 255) / 256, 256>>>(src, out);
}